// round 10
// baseline (speedup 1.0000x reference)
#include <cuda_runtime.h>
#include <cuda_bf16.h>
#include <cstdint>

// ============================================================================
// AdaBoost fused classifier via bf16 6-pass fp32 emulation on tensor cores,
// with fp64 rescue of near-zero logits (|l| < 1e-4) for exact sign decisions.
//   out[n] = sign( sum_e trunc(alpha_e) * (x[n]·W[e] + b[e] > 0) )
// ============================================================================

#define E_MAX   256
#define F_DIM   512
#define BM      128
#define BN      128
#define KC      64                 // bf16 elems per K-chunk -> 128B rows (SW128)
#define NCHUNK  (F_DIM / KC)       // 8
#define TILEB   (BM * 128)         // 16384 bytes per (stage,split) tile
#define NSPLIT  3
#define RESCUE_TAU 1e-4f
#define IDESC_BF16 0x08200490u     // dF32 | aBF16 | bBF16 | N=128 | M=128

// shared-memory layout (dynamic, same allocation both paths)
#define SM_TMEMP 0
#define SM_MBAR  8
#define SM_TS    32
#define SM_BS    544
#define SM_ACC   1056
#define SM_A     2048
#define SM_B     (2048 + 2 * NSPLIT * TILEB)
#define SM_TOTAL (SM_B + 2 * NSPLIT * TILEB)   // 198656 bytes

__device__ float g_t[E_MAX];
__device__ float g_bc[E_MAX];
__device__ int   g_idx[E_MAX];
__device__ int   g_nct;
__device__ float g_Wf[E_MAX * F_DIM];            // compacted fp32 W (rescue path)
// pre-swizzled bf16 W splits: [col_tile][split][chunk][16KB tile]
__device__ unsigned char g_Wb[2][NSPLIT][NCHUNK][TILEB];

// ---------------------------------------------------------------------------
// Common helpers
// ---------------------------------------------------------------------------
__device__ __forceinline__ uint32_t smem_u32(const void* p) {
    uint32_t a;
    asm("{ .reg .u64 t; cvta.to.shared.u64 t, %1; cvt.u32.u64 %0, t; }"
        : "=r"(a) : "l"(p));
    return a;
}
__device__ __forceinline__ uint32_t swz(uint32_t off) {
    return off ^ ((off >> 3) & 0x70);
}
__device__ __forceinline__ uint32_t pk(__nv_bfloat16 a, __nv_bfloat16 b) {
    return (uint32_t)__bfloat16_as_ushort(a)
         | ((uint32_t)__bfloat16_as_ushort(b) << 16);
}

// exact-sign rescue: fp64 dot of x row with compacted fp32 W row + bias
__device__ __noinline__ bool rescue_pred(const float* __restrict__ xrow,
                                         const float* __restrict__ wf,
                                         float bias) {
    double s0 = 0.0, s1 = 0.0, s2 = 0.0, s3 = 0.0;
    #pragma unroll 1
    for (int k = 0; k < F_DIM; k += 4) {
        s0 += (double)xrow[k + 0] * (double)wf[k + 0];
        s1 += (double)xrow[k + 1] * (double)wf[k + 1];
        s2 += (double)xrow[k + 2] * (double)wf[k + 2];
        s3 += (double)xrow[k + 3] * (double)wf[k + 3];
    }
    return ((s0 + s1) + (s2 + s3) + (double)bias) > 0.0;
}

// split a chunk of x (32 floats in f[8]) into 3 bf16 planes, store swizzled
__device__ __forceinline__ void split_store_A(const float4* f,
                                              unsigned char* smem,
                                              uint32_t abase, int xr, int xh) {
    #pragma unroll
    for (int g = 0; g < 4; g++) {
        float v[8];
        v[0] = f[2*g].x; v[1] = f[2*g].y; v[2] = f[2*g].z; v[3] = f[2*g].w;
        v[4] = f[2*g+1].x; v[5] = f[2*g+1].y; v[6] = f[2*g+1].z; v[7] = f[2*g+1].w;
        uint32_t w0[4], w1[4], w2[4];
        #pragma unroll
        for (int e2 = 0; e2 < 4; e2++) {
            float a = v[2*e2], bvv = v[2*e2+1];
            __nv_bfloat16 a0 = __float2bfloat16_rn(a);
            float ar = a - __bfloat162float(a0);
            __nv_bfloat16 a1 = __float2bfloat16_rn(ar);
            float ar2 = ar - __bfloat162float(a1);
            __nv_bfloat16 a2 = __float2bfloat16_rn(ar2);
            __nv_bfloat16 b0 = __float2bfloat16_rn(bvv);
            float br = bvv - __bfloat162float(b0);
            __nv_bfloat16 b1 = __float2bfloat16_rn(br);
            float br2 = br - __bfloat162float(b1);
            __nv_bfloat16 b2 = __float2bfloat16_rn(br2);
            w0[e2] = pk(a0, b0); w1[e2] = pk(a1, b1); w2[e2] = pk(a2, b2);
        }
        uint32_t sw = swz((uint32_t)(xr * 128 + (xh * 32 + g * 8) * 2));
        *(uint4*)(smem + abase + 0 * TILEB + sw) = make_uint4(w0[0], w0[1], w0[2], w0[3]);
        *(uint4*)(smem + abase + 1 * TILEB + sw) = make_uint4(w1[0], w1[1], w1[2], w1[3]);
        *(uint4*)(smem + abase + 2 * TILEB + sw) = make_uint4(w2[0], w2[1], w2[2], w2[3]);
    }
}

// ---------------------------------------------------------------------------
// mma.sync / ldmatrix / cp.async helpers (portable path)
// ---------------------------------------------------------------------------
__device__ __forceinline__ void ldsm4(uint32_t* r, uint32_t addr) {
    asm volatile("ldmatrix.sync.aligned.m8n8.x4.shared.b16 {%0,%1,%2,%3}, [%4];"
        : "=r"(r[0]), "=r"(r[1]), "=r"(r[2]), "=r"(r[3]) : "r"(addr));
}
__device__ __forceinline__ void mma16816(float* c, const uint32_t* a,
                                         uint32_t b0, uint32_t b1) {
    asm volatile("mma.sync.aligned.m16n8k16.row.col.f32.bf16.bf16.f32 "
        "{%0,%1,%2,%3}, {%4,%5,%6,%7}, {%8,%9}, {%0,%1,%2,%3};"
        : "+f"(c[0]), "+f"(c[1]), "+f"(c[2]), "+f"(c[3])
        : "r"(a[0]), "r"(a[1]), "r"(a[2]), "r"(a[3]), "r"(b0), "r"(b1));
}
__device__ __forceinline__ void cpasync16(uint32_t dst, const void* src) {
    asm volatile("cp.async.cg.shared.global [%0], [%1], 16;"
                 :: "r"(dst), "l"(src) : "memory");
}
__device__ __forceinline__ void cp_commit() {
    asm volatile("cp.async.commit_group;" ::: "memory");
}
__device__ __forceinline__ void cp_wait0() {
    asm volatile("cp.async.wait_group 0;" ::: "memory");
}

// ---------------------------------------------------------------------------
// tcgen05 helpers (only referenced under the arch-feature guard)
// ---------------------------------------------------------------------------
__device__ __forceinline__ uint32_t elect_one() {
    uint32_t r;
    asm volatile("{\n\t.reg .pred p;\n\telect.sync _|p, 0xFFFFFFFF;\n\t"
                 "selp.b32 %0, 1, 0, p;\n\t}" : "=r"(r));
    return r;
}
__device__ __forceinline__ void mbar_init(uint32_t a, uint32_t cnt) {
    asm volatile("mbarrier.init.shared.b64 [%0], %1;" :: "r"(a), "r"(cnt) : "memory");
}
__device__ __forceinline__ void mbar_wait(uint32_t a, uint32_t parity) {
    asm volatile("{\n\t.reg .pred P;\n\tWL%=: \n\t"
                 "mbarrier.try_wait.parity.acquire.cta.shared::cta.b64 P, [%0], %1, 0x989680;\n\t"
                 "@!P bra WL%=;\n\t}" :: "r"(a), "r"(parity) : "memory");
}
__device__ __forceinline__ void fence_proxy() {
    asm volatile("fence.proxy.async.shared::cta;" ::: "memory");
}
#if defined(__CUDA_ARCH_FEAT_SM103_ALL) || defined(__CUDA_ARCH_FEAT_SM100_ALL)
__device__ __forceinline__ void tm_alloc(uint32_t smem_dst, uint32_t ncols) {
    asm volatile("tcgen05.alloc.cta_group::1.sync.aligned.shared::cta.b32 [%0], %1;"
                 :: "r"(smem_dst), "r"(ncols) : "memory");
}
__device__ __forceinline__ void tm_relinquish() {
    asm volatile("tcgen05.relinquish_alloc_permit.cta_group::1.sync.aligned;");
}
__device__ __forceinline__ void tm_dealloc(uint32_t tmem, uint32_t ncols) {
    asm volatile("tcgen05.dealloc.cta_group::1.sync.aligned.b32 %0, %1;"
                 :: "r"(tmem), "r"(ncols));
}
__device__ __forceinline__ void tm_commit(uint32_t mbar) {
    asm volatile("tcgen05.commit.cta_group::1.mbarrier::arrive::one.shared::cluster.b64 [%0];"
                 :: "r"(mbar) : "memory");
}
__device__ __forceinline__ void tm_fence_after() {
    asm volatile("tcgen05.fence::after_thread_sync;" ::: "memory");
}
__device__ __forceinline__ void tm_fence_before() {
    asm volatile("tcgen05.fence::before_thread_sync;" ::: "memory");
}
__device__ __forceinline__ void tm_wait_ld() {
    asm volatile("tcgen05.wait::ld.sync.aligned;" ::: "memory");
}
__device__ __forceinline__ void mma_bf16_ss(uint32_t d, uint64_t ad, uint64_t bd,
                                            uint32_t en) {
    asm volatile("{\n\t.reg .pred p;\n\tsetp.ne.u32 p, %4, 0;\n\t"
                 "tcgen05.mma.cta_group::1.kind::f16 [%0], %1, %2, %3, "
                 "{%5, %5, %5, %5}, p;\n\t}"
                 :: "r"(d), "l"(ad), "l"(bd), "r"(IDESC_BF16), "r"(en), "r"(0u)
                 : "memory");
}
__device__ __forceinline__ uint64_t make_desc(uint32_t base) {
    const uint64_t C = (uint64_t(2) << 61) | (uint64_t(1) << 46)
                     | (uint64_t(64) << 32) | (uint64_t(1) << 16);
    return C | ((uint64_t)(base >> 4) & 0x3FFF);
}
#define LDTM_X32(r, addr)                                                      \
    asm volatile("tcgen05.ld.sync.aligned.32x32b.x32.b32 "                     \
        "{%0, %1, %2, %3, %4, %5, %6, %7, %8, %9, %10, %11, %12, %13, %14, %15,"\
        " %16, %17, %18, %19, %20, %21, %22, %23, %24, %25, %26, %27, %28, %29, %30, %31}, [%32];" \
        : "=r"((r)[0]), "=r"((r)[1]), "=r"((r)[2]), "=r"((r)[3]),              \
          "=r"((r)[4]), "=r"((r)[5]), "=r"((r)[6]), "=r"((r)[7]),              \
          "=r"((r)[8]), "=r"((r)[9]), "=r"((r)[10]), "=r"((r)[11]),            \
          "=r"((r)[12]), "=r"((r)[13]), "=r"((r)[14]), "=r"((r)[15]),          \
          "=r"((r)[16]), "=r"((r)[17]), "=r"((r)[18]), "=r"((r)[19]),          \
          "=r"((r)[20]), "=r"((r)[21]), "=r"((r)[22]), "=r"((r)[23]),          \
          "=r"((r)[24]), "=r"((r)[25]), "=r"((r)[26]), "=r"((r)[27]),          \
          "=r"((r)[28]), "=r"((r)[29]), "=r"((r)[30]), "=r"((r)[31])           \
        : "r"(addr))
#endif

// ---------------------------------------------------------------------------
// Kernel 1: deterministic compaction of estimators with trunc(alpha) != 0
// ---------------------------------------------------------------------------
__global__ void compact_kernel(const float* __restrict__ alphas,
                               const float* __restrict__ b) {
    int e = threadIdx.x;
    float t = truncf(alphas[e]);
    bool p = (t != 0.0f);

    unsigned mask = __ballot_sync(0xffffffffu, p);
    int warp = e >> 5, lane = e & 31;
    __shared__ int wcnt[8];
    if (lane == 0) wcnt[warp] = __popc(mask);
    __syncthreads();

    int off = 0;
    #pragma unroll
    for (int w = 0; w < 8; w++) if (w < warp) off += wcnt[w];
    int pos = off + __popc(mask & ((1u << lane) - 1u));
    if (p) { g_idx[pos] = e; g_t[pos] = t; g_bc[pos] = b[e]; }
    __syncthreads();

    int total = 0;
    #pragma unroll
    for (int w = 0; w < 8; w++) total += wcnt[w];

    for (int j = total + e; j < E_MAX; j += 256) {
        g_t[j] = 0.0f; g_bc[j] = 0.0f; g_idx[j] = 0;
    }
    if (e == 0) {
        int nct = (total + BN - 1) / BN;
        g_nct = (nct < 1) ? 1 : nct;
    }
}

// ---------------------------------------------------------------------------
// Kernel 2: gather + fp32 copy + bf16 3-way split + pre-swizzle of W tiles
// ---------------------------------------------------------------------------
__global__ void gather_split_kernel(const float* __restrict__ W) {
    int j  = blockIdx.x;          // slot 0..255
    int ct = j >> 7;              // col tile 0/1
    int r  = j & 127;             // row within B tile
    int src = g_idx[j];
    for (int k = threadIdx.x; k < F_DIM; k += blockDim.x) {
        float w = W[(size_t)src * F_DIM + k];
        g_Wf[(size_t)j * F_DIM + k] = w;               // fp32 copy for rescue
        __nv_bfloat16 h0 = __float2bfloat16_rn(w);
        float r1 = w - __bfloat162float(h0);
        __nv_bfloat16 h1 = __float2bfloat16_rn(r1);
        float r2 = r1 - __bfloat162float(h1);
        __nv_bfloat16 h2 = __float2bfloat16_rn(r2);
        int ch = k >> 6, kk = k & 63;
        uint32_t sw = swz((uint32_t)(r * 128 + kk * 2));
        *(__nv_bfloat16*)&g_Wb[ct][0][ch][sw] = h0;
        *(__nv_bfloat16*)&g_Wb[ct][1][ch][sw] = h1;
        *(__nv_bfloat16*)&g_Wb[ct][2][ch][sw] = h2;
    }
}

// ---------------------------------------------------------------------------
// Kernel 3: main GEMM + predicate (with fp64 rescue) + weighted sum + sign
// ---------------------------------------------------------------------------
__global__ __launch_bounds__(256, 1)
void adaboost_tc_kernel(const float* __restrict__ x, float* __restrict__ out) {
#if defined(__CUDA_ARCH_FEAT_SM103_ALL) || defined(__CUDA_ARCH_FEAT_SM100_ALL)
    // ======================= tcgen05 path =======================
    extern __shared__ __align__(1024) unsigned char smem[];
    const uint32_t sb = smem_u32(smem);
    const int tid = threadIdx.x, wid = tid >> 5, lid = tid & 31;
    const int row0 = blockIdx.x * BM;

    if (wid == 0) { tm_alloc(sb + SM_TMEMP, 128); tm_relinquish(); }
    if (tid == 0) { mbar_init(sb + SM_MBAR, 1); mbar_init(sb + SM_MBAR + 8, 1); }
    __syncthreads();
    uint32_t tmem;
    asm volatile("ld.shared.b32 %0, [%1];" : "=r"(tmem) : "r"(sb + SM_TMEMP));

    const int nct = g_nct;
    int issued[2] = {0, 0}, waited[2] = {0, 0}, phase[2] = {0, 0};
    float accv = 0.0f;

    const int xr = tid >> 1, xh = tid & 1;
    const float* xrow = x + (size_t)(row0 + xr) * F_DIM + xh * 32;

    for (int ct = 0; ct < nct; ct++) {
        if (tid < BN) {
            ((float*)(smem + SM_TS))[tid] = g_t[ct * BN + tid];
            ((float*)(smem + SM_BS))[tid] = g_bc[ct * BN + tid];
        }
        __syncthreads();

        for (int c = 0; c < NCHUNK; c++) {
            const int st = c & 1;
            while (waited[st] < issued[st]) {
                mbar_wait(sb + SM_MBAR + st * 8, (uint32_t)phase[st]);
                phase[st] ^= 1; waited[st]++;
            }

            const float* xp = xrow + c * KC;
            float4 f[8];
            #pragma unroll
            for (int q = 0; q < 8; q++) f[q] = *(const float4*)(xp + q * 4);

            const uint32_t abase = SM_A + st * NSPLIT * TILEB;
            split_store_A(f, smem, abase, xr, xh);

            const uint32_t bbase = SM_B + st * NSPLIT * TILEB;
            #pragma unroll
            for (int s = 0; s < NSPLIT; s++) {
                const uint4* ws = (const uint4*)&g_Wb[ct][s][c][0];
                uint4* wd = (uint4*)(smem + bbase + s * TILEB);
                #pragma unroll
                for (int q = 0; q < 4; q++) wd[tid + q * 256] = ws[tid + q * 256];
            }

            fence_proxy();
            __syncthreads();

            if (wid == 0 && elect_one()) {
                tm_fence_after();
                uint64_t ad[3], bd[3];
                #pragma unroll
                for (int s = 0; s < NSPLIT; s++) {
                    ad[s] = make_desc(sb + abase + s * TILEB);
                    bd[s] = make_desc(sb + bbase + s * TILEB);
                }
                const int ca[6] = {0, 0, 1, 1, 2, 0};
                const int cb[6] = {0, 1, 0, 1, 0, 2};
                #pragma unroll
                for (int m = 0; m < 6; m++) {
                    #pragma unroll
                    for (int k = 0; k < 4; k++) {
                        uint32_t en = (c == 0 && m == 0 && k == 0) ? 0u : 1u;
                        mma_bf16_ss(tmem, ad[ca[m]] + k * 2, bd[cb[m]] + k * 2, en);
                    }
                }
                tm_commit(sb + SM_MBAR + st * 8);
            }
            issued[st]++;
        }

        #pragma unroll
        for (int st = 0; st < 2; st++) {
            while (waited[st] < issued[st]) {
                mbar_wait(sb + SM_MBAR + st * 8, (uint32_t)phase[st]);
                phase[st] ^= 1; waited[st]++;
            }
        }
        tm_fence_after();

        if (wid < 4) {
            const float* tsp = (const float*)(smem + SM_TS);
            const float* bsp = (const float*)(smem + SM_BS);
            const int row = wid * 32 + lid;
            const float* xrw = x + (size_t)(row0 + row) * F_DIM;
            #pragma unroll
            for (int g = 0; g < 4; g++) {
                uint32_t d[32];
                LDTM_X32(d, tmem + g * 32);
                tm_wait_ld();
                #pragma unroll
                for (int cix = 0; cix < 32; cix++) {
                    int cc = g * 32 + cix;
                    float l = __uint_as_float(d[cix]) + bsp[cc];
                    bool p;
                    if (fabsf(l) < RESCUE_TAU)
                        p = rescue_pred(xrw, g_Wf + (size_t)(ct * BN + cc) * F_DIM,
                                        bsp[cc]);
                    else
                        p = (l > 0.0f);
                    if (p) accv += tsp[cc];
                }
            }
            tm_fence_before();
        }
        __syncthreads();
    }

    if (wid < 4) {
        int row = wid * 32 + lid;
        out[row0 + row] = (accv > 0.0f) ? 1.0f : ((accv < 0.0f) ? -1.0f : 0.0f);
    }
    __syncthreads();
    if (wid == 0) tm_dealloc(tmem, 128);

#else
    // ================== portable mma.sync path ==================
    extern __shared__ __align__(1024) unsigned char smem[];
    const uint32_t sb = smem_u32(smem);
    const int tid = threadIdx.x, wid = tid >> 5, lid = tid & 31;
    const int row0 = blockIdx.x * BM;
    const int m0 = (wid & 3) * 32;       // warp M offset
    const int n0 = (wid >> 2) * 64;      // warp N offset

    float* accRow = (float*)(smem + SM_ACC);
    if (tid < BM) accRow[tid] = 0.0f;

    const int nct = g_nct;
    const int xr = tid >> 1, xh = tid & 1;
    const float* xrow = x + (size_t)(row0 + xr) * F_DIM + xh * 32;

    const int lrow = ((lid >> 3) & 1) * 8 + (lid & 7);   // ldmatrix row-in-16
    const int lko  = (lid >> 4) << 3;                    // ldmatrix k offset
    const int ca[6] = {0, 0, 0, 1, 1, 2};
    const int cb[6] = {0, 1, 2, 0, 1, 0};

    for (int ct = 0; ct < nct; ct++) {
        if (tid < BN) {
            ((float*)(smem + SM_TS))[tid] = g_t[ct * BN + tid];
            ((float*)(smem + SM_BS))[tid] = g_bc[ct * BN + tid];
        }

        float acc[2][8][4];
        #pragma unroll
        for (int mi = 0; mi < 2; mi++)
            #pragma unroll
            for (int nj = 0; nj < 8; nj++)
                #pragma unroll
                for (int q = 0; q < 4; q++) acc[mi][nj][q] = 0.0f;

        // ---- prologue: chunk 0 into stage 0
        {
            #pragma unroll
            for (int q = 0; q < 12; q++) {
                int idx = tid + q * 256;
                int sp = idx >> 10, wi = idx & 1023;
                cpasync16(sb + SM_B + sp * TILEB + (uint32_t)wi * 16,
                          &g_Wb[ct][sp][0][wi * 16]);
            }
            cp_commit();
            float4 f[8];
            #pragma unroll
            for (int q = 0; q < 8; q++) f[q] = *(const float4*)(xrow + q * 4);
            split_store_A(f, smem, SM_A, xr, xh);
            cp_wait0();
            __syncthreads();
        }

        for (int c = 0; c < NCHUNK; c++) {
            const int s = c & 1, p = s ^ 1;
            const bool pf = (c + 1 < NCHUNK);
            float4 f[8];
            if (pf) {
                #pragma unroll
                for (int q = 0; q < 12; q++) {
                    int idx = tid + q * 256;
                    int sp = idx >> 10, wi = idx & 1023;
                    cpasync16(sb + SM_B + (uint32_t)p * NSPLIT * TILEB
                                 + (uint32_t)sp * TILEB + (uint32_t)wi * 16,
                              &g_Wb[ct][sp][c + 1][wi * 16]);
                }
                cp_commit();
                const float* xp = xrow + (c + 1) * KC;
                #pragma unroll
                for (int q = 0; q < 8; q++) f[q] = *(const float4*)(xp + q * 4);
            }

            // ---- consume stage s: 6 split-combos x 4 k-steps
            const uint32_t abase = sb + SM_A + (uint32_t)s * NSPLIT * TILEB;
            const uint32_t bbase = sb + SM_B + (uint32_t)s * NSPLIT * TILEB;
            #pragma unroll
            for (int m = 0; m < 6; m++) {
                uint32_t at = abase + ca[m] * TILEB;
                uint32_t bt = bbase + cb[m] * TILEB;
                #pragma unroll
                for (int k0 = 0; k0 < KC; k0 += 16) {
                    uint32_t af[2][4], bf[4][4];
                    #pragma unroll
                    for (int mi = 0; mi < 2; mi++)
                        ldsm4(af[mi], at + swz((uint32_t)((m0 + mi * 16 + lrow) * 128
                                                          + (k0 + lko) * 2)));
                    #pragma unroll
                    for (int jj = 0; jj < 4; jj++)
                        ldsm4(bf[jj], bt + swz((uint32_t)((n0 + jj * 16 + lrow) * 128
                                                          + (k0 + lko) * 2)));
                    #pragma unroll
                    for (int mi = 0; mi < 2; mi++)
                        #pragma unroll
                        for (int nj = 0; nj < 8; nj++)
                            mma16816(acc[mi][nj], af[mi],
                                     bf[nj >> 1][nj & 1], bf[nj >> 1][2 + (nj & 1)]);
                }
            }

            if (pf) {
                split_store_A(f, smem, SM_A + (uint32_t)p * NSPLIT * TILEB, xr, xh);
                cp_wait0();
            }
            __syncthreads();
        }

        // ---- epilogue: bias, predicate (+fp64 rescue), weighted sum, reduce
        {
            const float* tsp = (const float*)(smem + SM_TS);
            const float* bsp = (const float*)(smem + SM_BS);
            const int gid = lid >> 2;
            #pragma unroll
            for (int mi = 0; mi < 2; mi++) {
                const int ra = m0 + mi * 16 + gid;       // rows for d[0],d[1]
                const int rb = ra + 8;                   // rows for d[2],d[3]
                const float* xra = x + (size_t)(row0 + ra) * F_DIM;
                const float* xrb = x + (size_t)(row0 + rb) * F_DIM;
                float s0 = 0.0f, s1 = 0.0f;
                #pragma unroll
                for (int nj = 0; nj < 8; nj++) {
                    int cc = n0 + nj * 8 + (lid & 3) * 2;
                    float2 bv = *(const float2*)&bsp[cc];
                    float2 tv = *(const float2*)&tsp[cc];
                    const float* d = acc[mi][nj];
                    const size_t w0o = (size_t)(ct * BN + cc) * F_DIM;
                    const size_t w1o = (size_t)(ct * BN + cc + 1) * F_DIM;
                    float l;
                    bool pr;
                    l = d[0] + bv.x;
                    pr = (fabsf(l) < RESCUE_TAU) ? rescue_pred(xra, g_Wf + w0o, bv.x)
                                                 : (l > 0.0f);
                    if (pr) s0 += tv.x;
                    l = d[1] + bv.y;
                    pr = (fabsf(l) < RESCUE_TAU) ? rescue_pred(xra, g_Wf + w1o, bv.y)
                                                 : (l > 0.0f);
                    if (pr) s0 += tv.y;
                    l = d[2] + bv.x;
                    pr = (fabsf(l) < RESCUE_TAU) ? rescue_pred(xrb, g_Wf + w0o, bv.x)
                                                 : (l > 0.0f);
                    if (pr) s1 += tv.x;
                    l = d[3] + bv.y;
                    pr = (fabsf(l) < RESCUE_TAU) ? rescue_pred(xrb, g_Wf + w1o, bv.y)
                                                 : (l > 0.0f);
                    if (pr) s1 += tv.y;
                }
                s0 += __shfl_xor_sync(0xffffffffu, s0, 1);
                s0 += __shfl_xor_sync(0xffffffffu, s0, 2);
                s1 += __shfl_xor_sync(0xffffffffu, s1, 1);
                s1 += __shfl_xor_sync(0xffffffffu, s1, 2);
                if ((lid & 3) == 0) {
                    atomicAdd(&accRow[ra], s0);
                    atomicAdd(&accRow[rb], s1);
                }
            }
        }
        __syncthreads();
    }

    if (tid < BM) {
        float a = accRow[tid];
        out[row0 + tid] = (a > 0.0f) ? 1.0f : ((a < 0.0f) ? -1.0f : 0.0f);
    }
#endif
}

// ---------------------------------------------------------------------------
extern "C" void kernel_launch(void* const* d_in, const int* in_sizes, int n_in,
                              void* d_out, int out_size) {
    const float* x      = (const float*)d_in[0];   // [131072, 512]
    const float* W      = (const float*)d_in[1];   // [256, 512]
    const float* b      = (const float*)d_in[2];   // [256]
    const float* alphas = (const float*)d_in[3];   // [256]
    float* out = (float*)d_out;                    // [131072]

    int N = in_sizes[0] / F_DIM;

    cudaFuncSetAttribute(adaboost_tc_kernel,
                         cudaFuncAttributeMaxDynamicSharedMemorySize, SM_TOTAL);

    compact_kernel<<<1, 256>>>(alphas, b);
    gather_split_kernel<<<E_MAX, 128>>>(W);
    adaboost_tc_kernel<<<N / BM, 256, SM_TOTAL>>>(x, out);
}

// round 11
// speedup vs baseline: 14.1779x; 14.1779x over previous
#include <cuda_runtime.h>
#include <cuda_bf16.h>
#include <cstdint>

// ============================================================================
// AdaBoost fused classifier, bf16 3-pass fp32-emulated GEMM on tensor cores.
//   out[n] = sign( sum_e trunc(alpha_e) * (x[n]·W[e] + b[e] > 0) )
// Near-tie logits (|l| < TAU) are flagged and re-decided exactly (fp64) by a
// separate fixup kernel; a final pass rewrites the sign of affected rows.
// ============================================================================

#define E_MAX   256
#define F_DIM   512
#define BM      128
#define BN      128
#define KC      64                 // bf16 elems per K-chunk -> 128B rows (SW128)
#define NCHUNK  (F_DIM / KC)       // 8
#define TILEB   (BM * 128)         // 16KB per (stage,split) tile
#define NSPLIT  2
#define NTHREADS 512
#define RESCUE_TAU 3e-4f
#define MAXR    (1 << 20)

// shared memory layout
#define SM_TS    0
#define SM_BS    512
#define SM_ACC   1024
#define SM_A     2048
#define SM_B     (SM_A + 2 * NSPLIT * TILEB)      // 67584
#define SM_TOTAL (SM_B + 2 * NSPLIT * TILEB)      // 133120 bytes

__device__ float    g_t[E_MAX];
__device__ float    g_bc[E_MAX];
__device__ int      g_idx[E_MAX];
__device__ int      g_nct;
__device__ float    g_Wf[E_MAX * F_DIM];          // compacted fp32 W (rescue)
__device__ float    g_acc[131072];                // per-row integer-valued acc
__device__ int      g_nrescue;
__device__ uint32_t g_rescue[MAXR];               // (row<<9)|(slot<<1)|pred
// pre-swizzled bf16 W splits: [col_tile][split][chunk][16KB tile]
__device__ unsigned char g_Wb[2][NSPLIT][NCHUNK][TILEB];

// ---------------------------------------------------------------------------
// helpers
// ---------------------------------------------------------------------------
__device__ __forceinline__ uint32_t smem_u32(const void* p) {
    uint32_t a;
    asm("{ .reg .u64 t; cvta.to.shared.u64 t, %1; cvt.u32.u64 %0, t; }"
        : "=r"(a) : "l"(p));
    return a;
}
__device__ __forceinline__ uint32_t swz(uint32_t off) {
    return off ^ ((off >> 3) & 0x70);
}
__device__ __forceinline__ uint32_t pk(__nv_bfloat16 a, __nv_bfloat16 b) {
    return (uint32_t)__bfloat16_as_ushort(a)
         | ((uint32_t)__bfloat16_as_ushort(b) << 16);
}
__device__ __forceinline__ void ldsm4(uint32_t* r, uint32_t addr) {
    asm volatile("ldmatrix.sync.aligned.m8n8.x4.shared.b16 {%0,%1,%2,%3}, [%4];"
        : "=r"(r[0]), "=r"(r[1]), "=r"(r[2]), "=r"(r[3]) : "r"(addr));
}
__device__ __forceinline__ void mma16816(float* c, const uint32_t* a,
                                         uint32_t b0, uint32_t b1) {
    asm volatile("mma.sync.aligned.m16n8k16.row.col.f32.bf16.bf16.f32 "
        "{%0,%1,%2,%3}, {%4,%5,%6,%7}, {%8,%9}, {%0,%1,%2,%3};"
        : "+f"(c[0]), "+f"(c[1]), "+f"(c[2]), "+f"(c[3])
        : "r"(a[0]), "r"(a[1]), "r"(a[2]), "r"(a[3]), "r"(b0), "r"(b1));
}
__device__ __forceinline__ void cpasync16(uint32_t dst, const void* src) {
    asm volatile("cp.async.cg.shared.global [%0], [%1], 16;"
                 :: "r"(dst), "l"(src) : "memory");
}
__device__ __forceinline__ void cp_commit() {
    asm volatile("cp.async.commit_group;" ::: "memory");
}
__device__ __forceinline__ void cp_wait0() {
    asm volatile("cp.async.wait_group 0;" ::: "memory");
}

// 2-way split of 16 floats (4x float4), store both bf16 planes swizzled
__device__ __forceinline__ void split16(const float4* f, unsigned char* smem,
                                        uint32_t abase, int xr, int xq) {
    #pragma unroll
    for (int h = 0; h < 2; h++) {
        float v[8];
        v[0] = f[2*h].x;   v[1] = f[2*h].y;   v[2] = f[2*h].z;   v[3] = f[2*h].w;
        v[4] = f[2*h+1].x; v[5] = f[2*h+1].y; v[6] = f[2*h+1].z; v[7] = f[2*h+1].w;
        uint32_t p0[4], p1[4];
        #pragma unroll
        for (int e = 0; e < 4; e++) {
            float a = v[2*e], b = v[2*e+1];
            __nv_bfloat16 a0 = __float2bfloat16_rn(a);
            __nv_bfloat16 a1 = __float2bfloat16_rn(a - __bfloat162float(a0));
            __nv_bfloat16 b0 = __float2bfloat16_rn(b);
            __nv_bfloat16 b1 = __float2bfloat16_rn(b - __bfloat162float(b0));
            p0[e] = pk(a0, b0); p1[e] = pk(a1, b1);
        }
        uint32_t sw = swz((uint32_t)(xr * 128 + xq * 32 + h * 16));
        *(uint4*)(smem + abase + 0 * TILEB + sw) = make_uint4(p0[0], p0[1], p0[2], p0[3]);
        *(uint4*)(smem + abase + 1 * TILEB + sw) = make_uint4(p1[0], p1[1], p1[2], p1[3]);
    }
}

// ---------------------------------------------------------------------------
// Kernel 1: compaction (also resets the rescue counter each replay)
// ---------------------------------------------------------------------------
__global__ void compact_kernel(const float* __restrict__ alphas,
                               const float* __restrict__ b) {
    int e = threadIdx.x;
    float t = truncf(alphas[e]);
    bool p = (t != 0.0f);

    unsigned mask = __ballot_sync(0xffffffffu, p);
    int warp = e >> 5, lane = e & 31;
    __shared__ int wcnt[8];
    if (lane == 0) wcnt[warp] = __popc(mask);
    __syncthreads();

    int off = 0;
    #pragma unroll
    for (int w = 0; w < 8; w++) if (w < warp) off += wcnt[w];
    int pos = off + __popc(mask & ((1u << lane) - 1u));
    if (p) { g_idx[pos] = e; g_t[pos] = t; g_bc[pos] = b[e]; }
    __syncthreads();

    int total = 0;
    #pragma unroll
    for (int w = 0; w < 8; w++) total += wcnt[w];

    for (int j = total + e; j < E_MAX; j += 256) {
        g_t[j] = 0.0f; g_bc[j] = 0.0f; g_idx[j] = 0;
    }
    if (e == 0) {
        int nct = (total + BN - 1) / BN;
        g_nct = (nct < 1) ? 1 : nct;
        g_nrescue = 0;                       // reset per launch (graph replay!)
    }
}

// ---------------------------------------------------------------------------
// Kernel 2: gather + fp32 copy + bf16 2-way split + pre-swizzle
// ---------------------------------------------------------------------------
__global__ void gather_split_kernel(const float* __restrict__ W) {
    int j  = blockIdx.x;          // slot 0..255
    int ct = j >> 7;
    int r  = j & 127;
    int src = g_idx[j];
    for (int k = threadIdx.x; k < F_DIM; k += blockDim.x) {
        float w = W[(size_t)src * F_DIM + k];
        g_Wf[(size_t)j * F_DIM + k] = w;
        __nv_bfloat16 h0 = __float2bfloat16_rn(w);
        __nv_bfloat16 h1 = __float2bfloat16_rn(w - __bfloat162float(h0));
        int ch = k >> 6, kk = k & 63;
        uint32_t sw = swz((uint32_t)(r * 128 + kk * 2));
        *(__nv_bfloat16*)&g_Wb[ct][0][ch][sw] = h0;
        *(__nv_bfloat16*)&g_Wb[ct][1][ch][sw] = h1;
    }
}

// ---------------------------------------------------------------------------
// Kernel 3: main GEMM (mma.sync bf16, 3 passes) + flagged predicate epilogue
//   512 threads, 16 warps: warp tile 32(M) x 32(N)
// ---------------------------------------------------------------------------
__global__ __launch_bounds__(NTHREADS, 1)
void adaboost_main_kernel(const float* __restrict__ x, float* __restrict__ out) {
    extern __shared__ __align__(1024) unsigned char smem[];
    const uint32_t sb = smem_u32(smem);
    const int tid = threadIdx.x, wid = tid >> 5, lid = tid & 31;
    const int row0 = blockIdx.x * BM;
    const int m0 = (wid & 3) * 32;
    const int n0 = (wid >> 2) * 32;

    float* accRow = (float*)(smem + SM_ACC);
    if (tid < BM) accRow[tid] = 0.0f;

    const int nct = g_nct;
    const int xr = tid >> 2, xq = tid & 3;           // row, 16-float quarter
    const float* xbase = x + (size_t)(row0 + xr) * F_DIM + xq * 16;

    const int lrow = ((lid >> 3) & 1) * 8 + (lid & 7);
    const int lko  = (lid >> 4) << 3;
    const int ca[3] = {0, 0, 1};
    const int cb[3] = {0, 1, 0};

    for (int ct = 0; ct < nct; ct++) {
        if (tid < BN) {
            ((float*)(smem + SM_TS))[tid] = g_t[ct * BN + tid];
            ((float*)(smem + SM_BS))[tid] = g_bc[ct * BN + tid];
        }

        float acc[2][4][4];
        #pragma unroll
        for (int mi = 0; mi < 2; mi++)
            #pragma unroll
            for (int nj = 0; nj < 4; nj++)
                #pragma unroll
                for (int q = 0; q < 4; q++) acc[mi][nj][q] = 0.0f;

        // ---- prologue: chunk 0 into stage 0
        {
            #pragma unroll
            for (int q = 0; q < 4; q++) {
                int idx = tid + q * NTHREADS;
                int sp = idx >> 10, wi = idx & 1023;
                cpasync16(sb + SM_B + (uint32_t)sp * TILEB + (uint32_t)wi * 16,
                          &g_Wb[ct][sp][0][wi * 16]);
            }
            cp_commit();
            float4 f[4];
            #pragma unroll
            for (int q = 0; q < 4; q++) f[q] = *(const float4*)(xbase + q * 4);
            split16(f, smem, SM_A, xr, xq);
            cp_wait0();
            __syncthreads();
        }

        for (int c = 0; c < NCHUNK; c++) {
            const int s = c & 1, p = s ^ 1;
            const bool pf = (c + 1 < NCHUNK);
            float4 f[4];
            if (pf) {
                #pragma unroll
                for (int q = 0; q < 4; q++) {
                    int idx = tid + q * NTHREADS;
                    int sp = idx >> 10, wi = idx & 1023;
                    cpasync16(sb + SM_B + ((uint32_t)p * NSPLIT + sp) * TILEB
                                 + (uint32_t)wi * 16,
                              &g_Wb[ct][sp][c + 1][wi * 16]);
                }
                cp_commit();
                const float* xp = xbase + (c + 1) * KC;
                #pragma unroll
                for (int q = 0; q < 4; q++) f[q] = *(const float4*)(xp + q * 4);
            }

            // ---- consume stage s: 3 split-combos x 4 k-steps
            const uint32_t abase = sb + SM_A + (uint32_t)s * NSPLIT * TILEB;
            const uint32_t bbase = sb + SM_B + (uint32_t)s * NSPLIT * TILEB;
            #pragma unroll
            for (int m = 0; m < 3; m++) {
                uint32_t at = abase + ca[m] * TILEB;
                uint32_t bt = bbase + cb[m] * TILEB;
                #pragma unroll
                for (int k0 = 0; k0 < KC; k0 += 16) {
                    uint32_t af[2][4], bf[2][4];
                    #pragma unroll
                    for (int mi = 0; mi < 2; mi++)
                        ldsm4(af[mi], at + swz((uint32_t)((m0 + mi * 16 + lrow) * 128
                                                          + (k0 + lko) * 2)));
                    #pragma unroll
                    for (int jj = 0; jj < 2; jj++)
                        ldsm4(bf[jj], bt + swz((uint32_t)((n0 + jj * 16 + lrow) * 128
                                                          + (k0 + lko) * 2)));
                    #pragma unroll
                    for (int mi = 0; mi < 2; mi++)
                        #pragma unroll
                        for (int nj = 0; nj < 4; nj++)
                            mma16816(acc[mi][nj], af[mi],
                                     bf[nj >> 1][nj & 1], bf[nj >> 1][2 + (nj & 1)]);
                }
            }

            if (pf) {
                split16(f, smem, SM_A + (uint32_t)p * NSPLIT * TILEB, xr, xq);
                cp_wait0();
            }
            __syncthreads();
        }

        // ---- epilogue: bias, predicate, flag near-ties, weighted row sums
        {
            const float* tsp = (const float*)(smem + SM_TS);
            const float* bsp = (const float*)(smem + SM_BS);
            const int gid = lid >> 2, qd = lid & 3;
            #pragma unroll
            for (int mi = 0; mi < 2; mi++) {
                const int ra = m0 + mi * 16 + gid;
                const int rb = ra + 8;
                float s0 = 0.0f, s1 = 0.0f;
                #pragma unroll
                for (int nj = 0; nj < 4; nj++) {
                    int cc = n0 + nj * 8 + qd * 2;
                    float2 bv = *(const float2*)&bsp[cc];
                    float2 tv = *(const float2*)&tsp[cc];
                    const float* d = acc[mi][nj];
                    #pragma unroll
                    for (int q = 0; q < 4; q++) {
                        const int rr   = (q < 2) ? ra : rb;
                        const float bb = (q & 1) ? bv.y : bv.x;
                        const float tt = (q & 1) ? tv.y : tv.x;
                        float l = d[q] + bb;
                        bool pr = (l > 0.0f);
                        if (pr) { if (q < 2) s0 += tt; else s1 += tt; }
                        if (fabsf(l) < RESCUE_TAU) {
                            int slot = ct * BN + cc + (q & 1);
                            int ix = atomicAdd(&g_nrescue, 1);
                            if (ix < MAXR)
                                g_rescue[ix] = ((uint32_t)(row0 + rr) << 9)
                                             | ((uint32_t)slot << 1)
                                             | (pr ? 1u : 0u);
                        }
                    }
                }
                s0 += __shfl_xor_sync(0xffffffffu, s0, 1);
                s0 += __shfl_xor_sync(0xffffffffu, s0, 2);
                s1 += __shfl_xor_sync(0xffffffffu, s1, 1);
                s1 += __shfl_xor_sync(0xffffffffu, s1, 2);
                if (qd == 0) {
                    atomicAdd(&accRow[ra], s0);
                    atomicAdd(&accRow[rb], s1);
                }
            }
        }
        __syncthreads();
    }

    if (tid < BM) {
        float a = accRow[tid];
        int row = row0 + tid;
        g_acc[row] = a;
        out[row] = (a > 0.0f) ? 1.0f : ((a < 0.0f) ? -1.0f : 0.0f);
    }
}

// ---------------------------------------------------------------------------
// Kernel 4: fp64 fixup of flagged logits (one warp per entry)
// ---------------------------------------------------------------------------
__global__ void fixup_kernel(const float* __restrict__ x) {
    int nwarp = (gridDim.x * blockDim.x) >> 5;
    int gw = (blockIdx.x * blockDim.x + threadIdx.x) >> 5;
    int lid = threadIdx.x & 31;
    int nr = g_nrescue; if (nr > MAXR) nr = MAXR;

    for (int i = gw; i < nr; i += nwarp) {
        uint32_t e = g_rescue[i];
        int grow = (int)(e >> 9);
        int slot = (int)((e >> 1) & 255u);
        int p0   = (int)(e & 1u);
        const float* xrw = x + (size_t)grow * F_DIM;
        const float* wf  = g_Wf + (size_t)slot * F_DIM;
        double s = 0.0;
        #pragma unroll
        for (int j = 0; j < F_DIM / 32; j++) {
            int k = lid + j * 32;
            s += (double)xrw[k] * (double)wf[k];
        }
        #pragma unroll
        for (int o = 16; o > 0; o >>= 1)
            s += __shfl_xor_sync(0xffffffffu, s, o);
        int pe = (s + (double)g_bc[slot]) > 0.0 ? 1 : 0;
        if (lid == 0 && pe != p0) {
            float t = g_t[slot];
            atomicAdd(&g_acc[grow], pe ? t : -t);   // integer-valued: exact
        }
    }
}

// ---------------------------------------------------------------------------
// Kernel 5: rewrite sign of affected rows (idempotent)
// ---------------------------------------------------------------------------
__global__ void signfix_kernel(float* __restrict__ out) {
    int nr = g_nrescue; if (nr > MAXR) nr = MAXR;
    for (int i = blockIdx.x * blockDim.x + threadIdx.x; i < nr;
         i += gridDim.x * blockDim.x) {
        int grow = (int)(g_rescue[i] >> 9);
        float a = g_acc[grow];
        out[grow] = (a > 0.0f) ? 1.0f : ((a < 0.0f) ? -1.0f : 0.0f);
    }
}

// ---------------------------------------------------------------------------
extern "C" void kernel_launch(void* const* d_in, const int* in_sizes, int n_in,
                              void* d_out, int out_size) {
    const float* x      = (const float*)d_in[0];   // [131072, 512]
    const float* W      = (const float*)d_in[1];   // [256, 512]
    const float* b      = (const float*)d_in[2];   // [256]
    const float* alphas = (const float*)d_in[3];   // [256]
    float* out = (float*)d_out;                    // [131072]

    int N = in_sizes[0] / F_DIM;

    cudaFuncSetAttribute(adaboost_main_kernel,
                         cudaFuncAttributeMaxDynamicSharedMemorySize, SM_TOTAL);

    compact_kernel<<<1, 256>>>(alphas, b);
    gather_split_kernel<<<E_MAX, 128>>>(W);
    adaboost_main_kernel<<<N / BM, NTHREADS, SM_TOTAL>>>(x, out);
    fixup_kernel<<<128, 256>>>(x);
    signfix_kernel<<<64, 256>>>(out);
}